// round 15
// baseline (speedup 1.0000x reference)
#include <cuda_runtime.h>
#include <cuda_fp16.h>
#include <mma.h>
#include <math.h>

using namespace nvcuda;

#define N_NODES 150000
#define N_EDGES 2400000
#define F_IN 128
#define HID 32
#define SCAN_BS 256
#define SCAN_NB ((N_NODES + SCAN_BS - 1) / SCAN_BS)   // 586

#define EDGE_BLKS 2344        // 600000 edge-quads / 256 (rounded up)
#define X1_BLKS 2344          // ceil(150000/64), 64 rows/block (tensor core)
#define HIST_BLKS 1172        // 8 edges/thread

#define SX_STRIDE 136         // padded half stride

// Scratch (allocation-free rule: __device__ globals)
__device__ float  g_dinv[N_NODES];
__device__ __half g_tmp[(size_t)N_NODES * HID];    // fp16 messages (9.6 MB)
__device__ __half g_acc[(size_t)N_NODES * HID];
__device__ float  g_tmp3[N_NODES];
__device__ int    g_cnt[N_NODES];
__device__ int    g_rowptr[N_NODES + 1];
__device__ int    g_cursor[N_NODES];
__device__ int    g_bsum[1024];
__device__ int    g_csr_src[N_EDGES];

// accumulate 8 halves of an int4 into a[0..7]
__device__ __forceinline__ void acc8(float* a, int4 v) {
    float2 f0 = __half22float2(*(__half2*)&v.x);
    float2 f1 = __half22float2(*(__half2*)&v.y);
    float2 f2 = __half22float2(*(__half2*)&v.z);
    float2 f3 = __half22float2(*(__half2*)&v.w);
    a[0] += f0.x; a[1] += f0.y; a[2] += f1.x; a[3] += f1.y;
    a[4] += f2.x; a[5] += f2.y; a[6] += f3.x; a[7] += f3.y;
}

// ---------------- F1: hist (role 0) + wmma xform1 RAW (roles 1,2) ----------------
__global__ __launch_bounds__(256) void k_F1(const int* __restrict__ dst,
                                            const float* __restrict__ x,
                                            const float* __restrict__ W1) {
    __shared__ __half sX[64 * SX_STRIDE];    // 17408 B
    __shared__ __half sWt[32 * SX_STRIDE];   // 8704 B
    __shared__ float  sC[8 * 256];           // 8192 B
    int tid = threadIdx.x;
    int grp = blockIdx.x / 3;
    int role = blockIdx.x - grp * 3;
    if (role == 0) {
        int t = grp * 256 + tid;
        int q0 = t * 2;
        if (q0 < N_EDGES / 4) {
            int4 d = __ldg((const int4*)dst + q0);
            atomicAdd(&g_cnt[d.x], 1);
            atomicAdd(&g_cnt[d.y], 1);
            atomicAdd(&g_cnt[d.z], 1);
            atomicAdd(&g_cnt[d.w], 1);
        }
        if (q0 + 1 < N_EDGES / 4) {
            int4 d = __ldg((const int4*)dst + q0 + 1);
            atomicAdd(&g_cnt[d.x], 1);
            atomicAdd(&g_cnt[d.y], 1);
            atomicAdd(&g_cnt[d.z], 1);
            atomicAdd(&g_cnt[d.w], 1);
        }
        return;
    }
    int xb = grp * 2 + (role - 1);
    int row0 = xb * 64;
    {
        const float4* xv = (const float4*)(x + (size_t)row0 * F_IN);
#pragma unroll
        for (int i = 0; i < 8; i++) {
            int idx = tid + i * 256;
            int r = idx >> 5;
            int c = idx & 31;
            float4 v = make_float4(0.f, 0.f, 0.f, 0.f);
            if (row0 + r < N_NODES) v = __ldg(xv + idx);
            int off = r * SX_STRIDE + c * 4;
            *(__half2*)&sX[off]     = __floats2half2_rn(v.x, v.y);
            *(__half2*)&sX[off + 2] = __floats2half2_rn(v.z, v.w);
        }
    }
    for (int i = tid; i < F_IN * HID; i += 256) {
        int k = i >> 5;
        int n = i & 31;
        sWt[n * SX_STRIDE + k] = __float2half_rn(W1[i]);
    }
    __syncthreads();

    int w = tid >> 5, l = tid & 31;
    int m0 = (w & 3) * 16;
    int n0 = (w >> 2) * 16;

    wmma::fragment<wmma::matrix_a, 16, 16, 16, __half, wmma::row_major> afrag;
    wmma::fragment<wmma::matrix_b, 16, 16, 16, __half, wmma::col_major> bfrag;
    wmma::fragment<wmma::accumulator, 16, 16, 16, float> cfrag;
    wmma::fill_fragment(cfrag, 0.0f);
#pragma unroll
    for (int ks = 0; ks < 8; ks++) {
        wmma::load_matrix_sync(afrag, &sX[m0 * SX_STRIDE + ks * 16], SX_STRIDE);
        wmma::load_matrix_sync(bfrag, &sWt[n0 * SX_STRIDE + ks * 16], SX_STRIDE);
        wmma::mma_sync(cfrag, afrag, bfrag, cfrag);
    }
    wmma::store_matrix_sync(&sC[w * 256], cfrag, 16, wmma::mem_row_major);
    __syncwarp();
    for (int idx = l; idx < 128; idx += 32) {
        int r = idx >> 3;
        int c = (idx & 7) * 2;
        int row = row0 + m0 + r;
        if (row < N_NODES) {
            float v0 = sC[w * 256 + r * 16 + c];
            float v1 = sC[w * 256 + r * 16 + c + 1];
            *(__half2*)&g_tmp[(size_t)row * HID + n0 + c] = __floats2half2_rn(v0, v1);
        }
    }
}

// ---------------- scan A ----------------
__global__ void k_scan_a() {
    __shared__ int wsum[8];
    int tid = threadIdx.x;
    int lane = tid & 31, w = tid >> 5;
    int i = blockIdx.x * SCAN_BS + tid;
    int v = (i < N_NODES) ? g_cnt[i] : 0;
    int s = v;
#pragma unroll
    for (int o = 1; o < 32; o <<= 1) {
        int t = __shfl_up_sync(0xffffffffu, s, o);
        if (lane >= o) s += t;
    }
    if (lane == 31) wsum[w] = s;
    __syncthreads();
    if (w == 0 && lane < 8) {
        int ws = wsum[lane];
#pragma unroll
        for (int o = 1; o < 8; o <<= 1) {
            int t = __shfl_up_sync(0xffu, ws, o);
            if (lane >= o) ws += t;
        }
        wsum[lane] = ws;
    }
    __syncthreads();
    int incl = s + (w > 0 ? wsum[w - 1] : 0);
    if (i < N_NODES) g_rowptr[i] = incl - v;
    if (tid == SCAN_BS - 1) g_bsum[blockIdx.x] = incl;
}

// ---------------- scan C (fused B) ----------------
__global__ void k_scan_c() {
    __shared__ int red[8];
    __shared__ int s_off;
    int tid = threadIdx.x;
    int lane = tid & 31, w = tid >> 5;
    int blk = blockIdx.x;
    int p = 0;
    for (int j = tid; j < blk; j += 256) p += g_bsum[j];
#pragma unroll
    for (int o = 16; o > 0; o >>= 1) p += __shfl_down_sync(0xffffffffu, p, o);
    if (lane == 0) red[w] = p;
    __syncthreads();
    if (tid == 0) {
        int t = 0;
#pragma unroll
        for (int k = 0; k < 8; k++) t += red[k];
        s_off = t;
    }
    __syncthreads();
    int off = s_off;
    int i = blk * 256 + tid;
    if (i < N_NODES) {
        int r = g_rowptr[i] + off;
        g_rowptr[i] = r;
        g_cursor[i] = r;
        g_dinv[i] = rsqrtf((float)(g_cnt[i] + 1));
    }
    if (i == 0) g_rowptr[N_NODES] = N_EDGES;
}

// ---------------- F2: interleaved fill (even) + dinv-scale of g_tmp (odd) ----------------
__global__ __launch_bounds__(256) void k_F2(const int* __restrict__ src,
                                            const int* __restrict__ dst) {
    int tid = threadIdx.x;
    int half_idx = blockIdx.x >> 1;
    if ((blockIdx.x & 1) == 0) {
        int t = half_idx * 256 + tid;
        if (t < N_EDGES / 4) {
            int4 s = __ldg((const int4*)src + t);
            int4 d = __ldg((const int4*)dst + t);
            g_csr_src[atomicAdd(&g_cursor[d.x], 1)] = s.x;
            g_csr_src[atomicAdd(&g_cursor[d.y], 1)] = s.y;
            g_csr_src[atomicAdd(&g_cursor[d.z], 1)] = s.z;
            g_csr_src[atomicAdd(&g_cursor[d.w], 1)] = s.w;
        }
    } else {
        int i = half_idx * 256 + tid;
        if (i < 600000) {
            int4* tv = (int4*)g_tmp;
            int4 raw = tv[i];
            float di = g_dinv[i >> 2];
            __half2* h = (__half2*)&raw;
            __half2 d2 = __float2half2_rn(di);
#pragma unroll
            for (int k = 0; k < 4; k++) h[k] = __hmul2(h[k], d2);
            tv[i] = raw;
        }
    }
}

// ---------------- fused: agg(L1) + relu + @W2 + scale -> g_acc (fp16) ----------------
// 8 edges/warp-iter: lane = eidx*4 + fg; each lane gathers int4 (8 halves).
__global__ void k_agg_xf2(const float* __restrict__ W2, const float* __restrict__ b1) {
    __shared__ float sW[HID * HID];
    __shared__ float sy[8][HID];
    int tid = threadIdx.x;  // 256
    for (int i = tid; i < HID * HID; i += 256) sW[i] = W2[i];
    __syncthreads();
    int w = tid >> 5, lane = tid & 31;
    int n = blockIdx.x * 8 + w;
    if (n >= N_NODES) return;  // warp-uniform
    int eidx = lane >> 2, fg = lane & 3;
    int e = g_rowptr[n];
    int e1 = g_rowptr[n + 1];
    float a[8] = {0, 0, 0, 0, 0, 0, 0, 0};
    for (; e + 16 <= e1; e += 16) {
        int s0 = g_csr_src[e + eidx];
        int s1 = g_csr_src[e + 8 + eidx];
        int4 v0 = *(const int4*)(g_tmp + (size_t)s0 * HID + fg * 8);
        int4 v1 = *(const int4*)(g_tmp + (size_t)s1 * HID + fg * 8);
        acc8(a, v0);
        acc8(a, v1);
    }
    if (e + 8 <= e1) {
        int s = g_csr_src[e + eidx];
        int4 v = *(const int4*)(g_tmp + (size_t)s * HID + fg * 8);
        acc8(a, v);
        e += 8;
    }
    if (eidx < e1 - e) {
        int s = g_csr_src[e + eidx];
        int4 v = *(const int4*)(g_tmp + (size_t)s * HID + fg * 8);
        acc8(a, v);
    }
#pragma unroll
    for (int o = 4; o <= 16; o <<= 1) {
#pragma unroll
        for (int j = 0; j < 8; j++) a[j] += __shfl_xor_sync(0xffffffffu, a[j], o);
    }
    // self loop (after reduction: each lane holds full sums for its fg features)
    {
        int4 v = *(const int4*)(g_tmp + (size_t)n * HID + fg * 8);
        acc8(a, v);
    }
    float di = g_dinv[n];
    if (eidx == 0) {
        float4 bv0 = *(const float4*)(b1 + fg * 8);
        float4 bv1 = *(const float4*)(b1 + fg * 8 + 4);
        float4 y0, y1;
        y0.x = fmaxf(fmaf(di, a[0], bv0.x), 0.0f);
        y0.y = fmaxf(fmaf(di, a[1], bv0.y), 0.0f);
        y0.z = fmaxf(fmaf(di, a[2], bv0.z), 0.0f);
        y0.w = fmaxf(fmaf(di, a[3], bv0.w), 0.0f);
        y1.x = fmaxf(fmaf(di, a[4], bv1.x), 0.0f);
        y1.y = fmaxf(fmaf(di, a[5], bv1.y), 0.0f);
        y1.z = fmaxf(fmaf(di, a[6], bv1.z), 0.0f);
        y1.w = fmaxf(fmaf(di, a[7], bv1.w), 0.0f);
        *(float4*)&sy[w][fg * 8]     = y0;
        *(float4*)&sy[w][fg * 8 + 4] = y1;
    }
    __syncwarp();
    float t = 0.0f;
#pragma unroll
    for (int k = 0; k < HID; k++) t = fmaf(sy[w][k], sW[k * HID + lane], t);
    g_acc[(size_t)n * HID + lane] = __float2half_rn(di * t);
}

// ---------------- fused: agg(L2) + relu + dot W3 + scale -> g_tmp3 ----------------
__global__ void k_agg_xf3(const float* __restrict__ W3, const float* __restrict__ b2) {
    int tid = threadIdx.x;
    int w = tid >> 5, lane = tid & 31;
    int n = blockIdx.x * 8 + w;
    if (n >= N_NODES) return;  // warp-uniform
    int eidx = lane >> 2, fg = lane & 3;
    int e = g_rowptr[n];
    int e1 = g_rowptr[n + 1];
    float a[8] = {0, 0, 0, 0, 0, 0, 0, 0};
    for (; e + 16 <= e1; e += 16) {
        int s0 = g_csr_src[e + eidx];
        int s1 = g_csr_src[e + 8 + eidx];
        int4 v0 = *(const int4*)(g_acc + (size_t)s0 * HID + fg * 8);
        int4 v1 = *(const int4*)(g_acc + (size_t)s1 * HID + fg * 8);
        acc8(a, v0);
        acc8(a, v1);
    }
    if (e + 8 <= e1) {
        int s = g_csr_src[e + eidx];
        int4 v = *(const int4*)(g_acc + (size_t)s * HID + fg * 8);
        acc8(a, v);
        e += 8;
    }
    if (eidx < e1 - e) {
        int s = g_csr_src[e + eidx];
        int4 v = *(const int4*)(g_acc + (size_t)s * HID + fg * 8);
        acc8(a, v);
    }
#pragma unroll
    for (int o = 4; o <= 16; o <<= 1) {
#pragma unroll
        for (int j = 0; j < 8; j++) a[j] += __shfl_xor_sync(0xffffffffu, a[j], o);
    }
    // self loop
    {
        int4 v = *(const int4*)(g_acc + (size_t)n * HID + fg * 8);
        acc8(a, v);
    }
    float di = g_dinv[n];
    float4 bv0 = *(const float4*)(b2 + fg * 8);
    float4 bv1 = *(const float4*)(b2 + fg * 8 + 4);
    float4 wv0 = *(const float4*)(W3 + fg * 8);
    float4 wv1 = *(const float4*)(W3 + fg * 8 + 4);
    float t = fmaxf(fmaf(di, a[0], bv0.x), 0.0f) * wv0.x
            + fmaxf(fmaf(di, a[1], bv0.y), 0.0f) * wv0.y
            + fmaxf(fmaf(di, a[2], bv0.z), 0.0f) * wv0.z
            + fmaxf(fmaf(di, a[3], bv0.w), 0.0f) * wv0.w
            + fmaxf(fmaf(di, a[4], bv1.x), 0.0f) * wv1.x
            + fmaxf(fmaf(di, a[5], bv1.y), 0.0f) * wv1.y
            + fmaxf(fmaf(di, a[6], bv1.z), 0.0f) * wv1.z
            + fmaxf(fmaf(di, a[7], bv1.w), 0.0f) * wv1.w;
    // sum across fg groups (bits 0-1 of lane)
    t += __shfl_xor_sync(0xffffffffu, t, 1);
    t += __shfl_xor_sync(0xffffffffu, t, 2);
    if (lane == 0) g_tmp3[n] = di * t;
}

// ---------------- scalar gather + final sigmoid ----------------
__global__ void k_agg1_final(const float* __restrict__ b3, float* __restrict__ out) {
    int n = blockIdx.x * blockDim.x + threadIdx.x;
    if (n >= N_NODES) return;
    int e = g_rowptr[n];
    int e1 = g_rowptr[n + 1];
    float a = g_tmp3[n];  // self loop
    for (; e + 4 <= e1; e += 4) {
        float v0 = g_tmp3[g_csr_src[e + 0]];
        float v1 = g_tmp3[g_csr_src[e + 1]];
        float v2 = g_tmp3[g_csr_src[e + 2]];
        float v3 = g_tmp3[g_csr_src[e + 3]];
        a += (v0 + v1) + (v2 + v3);
    }
    for (; e < e1; e++) a += g_tmp3[g_csr_src[e]];
    float z = fmaf(g_dinv[n], a, b3[0]);
    out[n] = 1.0f / (1.0f + __expf(-z));
}

extern "C" void kernel_launch(void* const* d_in, const int* in_sizes, int n_in,
                              void* d_out, int out_size) {
    // Resolve inputs by element count — robust to metadata ordering.
    int ix = -1, ie = -1, iw1 = -1, iw2 = -1, ib3 = -1;
    int i32[3], n32 = 0;
    for (int i = 0; i < n_in; i++) {
        switch (in_sizes[i]) {
            case 19200000: ix = i; break;
            case 4800000:  ie = i; break;
            case 4096:     iw1 = i; break;
            case 1024:     iw2 = i; break;
            case 1:        ib3 = i; break;
            case 32:       if (n32 < 3) i32[n32++] = i; break;
            default: break;
        }
    }
    int ib1, ib2, iw3;
    if (ie == 1) {  // dict order: x, edge_index, W1, b1, W2, b2, W3, b3
        ib1 = i32[0]; ib2 = i32[1]; iw3 = i32[2];
    } else {        // alphabetical: W1, W2, W3, b1, b2, b3, edge_index, x
        iw3 = i32[0]; ib1 = i32[1]; ib2 = i32[2];
    }

    const float* x  = (const float*)d_in[ix];
    const int* ei   = (const int*)d_in[ie];   // [2, E] int32
    const float* W1 = (const float*)d_in[iw1];
    const float* b1 = (const float*)d_in[ib1];
    const float* W2 = (const float*)d_in[iw2];
    const float* b2 = (const float*)d_in[ib2];
    const float* W3 = (const float*)d_in[iw3];
    const float* b3 = (const float*)d_in[ib3];
    float* out = (float*)d_out;

    const int* src = ei;
    const int* dst = ei + N_EDGES;

    const int T = 256;
    int nblk_nodes = (N_NODES + T - 1) / T;
    int nblk_rows8 = (N_NODES + 7) / 8;

    // zero counters via memset node (graph-capturable)
    void* cnt_ptr = nullptr;
    cudaGetSymbolAddress(&cnt_ptr, g_cnt);
    cudaMemsetAsync(cnt_ptr, 0, N_NODES * sizeof(int), 0);

    // F1: hist (1/3 of blocks) + wmma xform1 raw (2/3)
    k_F1<<<3 * HIST_BLKS, T>>>(dst, x, W1);
    k_scan_a<<<SCAN_NB, SCAN_BS>>>();
    k_scan_c<<<SCAN_NB, SCAN_BS>>>();   // fused scan_b + scan_c
    // F2: fill (even) + dinv-scale of g_tmp (odd)
    k_F2<<<2 * EDGE_BLKS, T>>>(src, dst);

    k_agg_xf2<<<nblk_rows8, T>>>(W2, b1);    // agg L1 + relu + @W2
    k_agg_xf3<<<nblk_rows8, T>>>(W3, b2);    // agg L2 + relu + dot W3
    k_agg1_final<<<nblk_nodes, T>>>(b3, out);
}

// round 16
// speedup vs baseline: 1.0013x; 1.0013x over previous
#include <cuda_runtime.h>
#include <cuda_fp16.h>
#include <mma.h>
#include <math.h>

using namespace nvcuda;

#define N_NODES 150000
#define N_EDGES 2400000
#define F_IN 128
#define HID 32
#define SCAN_BS 256
#define SCAN_NB ((N_NODES + SCAN_BS - 1) / SCAN_BS)   // 586

#define EDGE_BLKS 2344        // 600000 edge-quads / 256 (rounded up)
#define X1_BLKS 2344          // ceil(150000/64), 64 rows/block (tensor core)
#define HIST_BLKS 1172        // 8 edges/thread

#define SX_STRIDE 136         // padded half stride

// Scratch (allocation-free rule: __device__ globals)
__device__ float  g_dinv[N_NODES];
__device__ __half g_tmp[(size_t)N_NODES * HID];    // fp16 messages (9.6 MB)
__device__ __half g_acc[(size_t)N_NODES * HID];
__device__ float  g_tmp3[N_NODES];
__device__ int    g_cnt[N_NODES];
__device__ int    g_rowptr[N_NODES + 1];
__device__ int    g_cursor[N_NODES];
__device__ int    g_bsum[1024];
__device__ int    g_csr_src[N_EDGES];

// accumulate 8 halves of an int4 into a[0..7]
__device__ __forceinline__ void acc8(float* a, int4 v) {
    float2 f0 = __half22float2(*(__half2*)&v.x);
    float2 f1 = __half22float2(*(__half2*)&v.y);
    float2 f2 = __half22float2(*(__half2*)&v.z);
    float2 f3 = __half22float2(*(__half2*)&v.w);
    a[0] += f0.x; a[1] += f0.y; a[2] += f1.x; a[3] += f1.y;
    a[4] += f2.x; a[5] += f2.y; a[6] += f3.x; a[7] += f3.y;
}

// ---------------- F1: hist (role 0) + wmma xform1 RAW (roles 1,2) ----------------
__global__ __launch_bounds__(256) void k_F1(const int* __restrict__ dst,
                                            const float* __restrict__ x,
                                            const float* __restrict__ W1) {
    __shared__ __half sX[64 * SX_STRIDE];    // 17408 B
    __shared__ __half sWt[32 * SX_STRIDE];   // 8704 B
    __shared__ float  sC[8 * 256];           // 8192 B
    int tid = threadIdx.x;
    int grp = blockIdx.x / 3;
    int role = blockIdx.x - grp * 3;
    if (role == 0) {
        int t = grp * 256 + tid;
        int q0 = t * 2;
        if (q0 < N_EDGES / 4) {
            int4 d = __ldg((const int4*)dst + q0);
            atomicAdd(&g_cnt[d.x], 1);
            atomicAdd(&g_cnt[d.y], 1);
            atomicAdd(&g_cnt[d.z], 1);
            atomicAdd(&g_cnt[d.w], 1);
        }
        if (q0 + 1 < N_EDGES / 4) {
            int4 d = __ldg((const int4*)dst + q0 + 1);
            atomicAdd(&g_cnt[d.x], 1);
            atomicAdd(&g_cnt[d.y], 1);
            atomicAdd(&g_cnt[d.z], 1);
            atomicAdd(&g_cnt[d.w], 1);
        }
        return;
    }
    int xb = grp * 2 + (role - 1);
    int row0 = xb * 64;
    {
        const float4* xv = (const float4*)(x + (size_t)row0 * F_IN);
#pragma unroll
        for (int i = 0; i < 8; i++) {
            int idx = tid + i * 256;
            int r = idx >> 5;
            int c = idx & 31;
            float4 v = make_float4(0.f, 0.f, 0.f, 0.f);
            if (row0 + r < N_NODES) v = __ldg(xv + idx);
            int off = r * SX_STRIDE + c * 4;
            *(__half2*)&sX[off]     = __floats2half2_rn(v.x, v.y);
            *(__half2*)&sX[off + 2] = __floats2half2_rn(v.z, v.w);
        }
    }
    for (int i = tid; i < F_IN * HID; i += 256) {
        int k = i >> 5;
        int n = i & 31;
        sWt[n * SX_STRIDE + k] = __float2half_rn(W1[i]);
    }
    __syncthreads();

    int w = tid >> 5, l = tid & 31;
    int m0 = (w & 3) * 16;
    int n0 = (w >> 2) * 16;

    wmma::fragment<wmma::matrix_a, 16, 16, 16, __half, wmma::row_major> afrag;
    wmma::fragment<wmma::matrix_b, 16, 16, 16, __half, wmma::col_major> bfrag;
    wmma::fragment<wmma::accumulator, 16, 16, 16, float> cfrag;
    wmma::fill_fragment(cfrag, 0.0f);
#pragma unroll
    for (int ks = 0; ks < 8; ks++) {
        wmma::load_matrix_sync(afrag, &sX[m0 * SX_STRIDE + ks * 16], SX_STRIDE);
        wmma::load_matrix_sync(bfrag, &sWt[n0 * SX_STRIDE + ks * 16], SX_STRIDE);
        wmma::mma_sync(cfrag, afrag, bfrag, cfrag);
    }
    wmma::store_matrix_sync(&sC[w * 256], cfrag, 16, wmma::mem_row_major);
    __syncwarp();
    for (int idx = l; idx < 128; idx += 32) {
        int r = idx >> 3;
        int c = (idx & 7) * 2;
        int row = row0 + m0 + r;
        if (row < N_NODES) {
            float v0 = sC[w * 256 + r * 16 + c];
            float v1 = sC[w * 256 + r * 16 + c + 1];
            *(__half2*)&g_tmp[(size_t)row * HID + n0 + c] = __floats2half2_rn(v0, v1);
        }
    }
}

// ---------------- scan A ----------------
__global__ void k_scan_a() {
    __shared__ int wsum[8];
    int tid = threadIdx.x;
    int lane = tid & 31, w = tid >> 5;
    int i = blockIdx.x * SCAN_BS + tid;
    int v = (i < N_NODES) ? g_cnt[i] : 0;
    int s = v;
#pragma unroll
    for (int o = 1; o < 32; o <<= 1) {
        int t = __shfl_up_sync(0xffffffffu, s, o);
        if (lane >= o) s += t;
    }
    if (lane == 31) wsum[w] = s;
    __syncthreads();
    if (w == 0 && lane < 8) {
        int ws = wsum[lane];
#pragma unroll
        for (int o = 1; o < 8; o <<= 1) {
            int t = __shfl_up_sync(0xffu, ws, o);
            if (lane >= o) ws += t;
        }
        wsum[lane] = ws;
    }
    __syncthreads();
    int incl = s + (w > 0 ? wsum[w - 1] : 0);
    if (i < N_NODES) g_rowptr[i] = incl - v;
    if (tid == SCAN_BS - 1) g_bsum[blockIdx.x] = incl;
}

// ---------------- scan C (fused B) ----------------
__global__ void k_scan_c() {
    __shared__ int red[8];
    __shared__ int s_off;
    int tid = threadIdx.x;
    int lane = tid & 31, w = tid >> 5;
    int blk = blockIdx.x;
    int p = 0;
    for (int j = tid; j < blk; j += 256) p += g_bsum[j];
#pragma unroll
    for (int o = 16; o > 0; o >>= 1) p += __shfl_down_sync(0xffffffffu, p, o);
    if (lane == 0) red[w] = p;
    __syncthreads();
    if (tid == 0) {
        int t = 0;
#pragma unroll
        for (int k = 0; k < 8; k++) t += red[k];
        s_off = t;
    }
    __syncthreads();
    int off = s_off;
    int i = blk * 256 + tid;
    if (i < N_NODES) {
        int r = g_rowptr[i] + off;
        g_rowptr[i] = r;
        g_cursor[i] = r;
        g_dinv[i] = rsqrtf((float)(g_cnt[i] + 1));
    }
    if (i == 0) g_rowptr[N_NODES] = N_EDGES;
}

// ---------------- F2: interleaved fill (even) + dinv-scale of g_tmp (odd) ----------------
__global__ __launch_bounds__(256) void k_F2(const int* __restrict__ src,
                                            const int* __restrict__ dst) {
    int tid = threadIdx.x;
    int half_idx = blockIdx.x >> 1;
    if ((blockIdx.x & 1) == 0) {
        int t = half_idx * 256 + tid;
        if (t < N_EDGES / 4) {
            int4 s = __ldg((const int4*)src + t);
            int4 d = __ldg((const int4*)dst + t);
            g_csr_src[atomicAdd(&g_cursor[d.x], 1)] = s.x;
            g_csr_src[atomicAdd(&g_cursor[d.y], 1)] = s.y;
            g_csr_src[atomicAdd(&g_cursor[d.z], 1)] = s.z;
            g_csr_src[atomicAdd(&g_cursor[d.w], 1)] = s.w;
        }
    } else {
        int i = half_idx * 256 + tid;
        if (i < 600000) {
            int4* tv = (int4*)g_tmp;
            int4 raw = tv[i];
            float di = g_dinv[i >> 2];
            __half2* h = (__half2*)&raw;
            __half2 d2 = __float2half2_rn(di);
#pragma unroll
            for (int k = 0; k < 4; k++) h[k] = __hmul2(h[k], d2);
            tv[i] = raw;
        }
    }
}

// ---------------- fused: agg(L1) + relu + @W2 + scale -> g_acc (fp16) ----------------
// 8 edges/warp-iter: lane = eidx*4 + fg; each lane gathers int4 (8 halves).
__global__ void k_agg_xf2(const float* __restrict__ W2, const float* __restrict__ b1) {
    __shared__ float sW[HID * HID];
    __shared__ float sy[8][HID];
    int tid = threadIdx.x;  // 256
    for (int i = tid; i < HID * HID; i += 256) sW[i] = W2[i];
    __syncthreads();
    int w = tid >> 5, lane = tid & 31;
    int n = blockIdx.x * 8 + w;
    if (n >= N_NODES) return;  // warp-uniform
    int eidx = lane >> 2, fg = lane & 3;
    int e = g_rowptr[n];
    int e1 = g_rowptr[n + 1];
    float a[8] = {0, 0, 0, 0, 0, 0, 0, 0};
    for (; e + 16 <= e1; e += 16) {
        int s0 = g_csr_src[e + eidx];
        int s1 = g_csr_src[e + 8 + eidx];
        int4 v0 = *(const int4*)(g_tmp + (size_t)s0 * HID + fg * 8);
        int4 v1 = *(const int4*)(g_tmp + (size_t)s1 * HID + fg * 8);
        acc8(a, v0);
        acc8(a, v1);
    }
    if (e + 8 <= e1) {
        int s = g_csr_src[e + eidx];
        int4 v = *(const int4*)(g_tmp + (size_t)s * HID + fg * 8);
        acc8(a, v);
        e += 8;
    }
    if (eidx < e1 - e) {
        int s = g_csr_src[e + eidx];
        int4 v = *(const int4*)(g_tmp + (size_t)s * HID + fg * 8);
        acc8(a, v);
    }
#pragma unroll
    for (int o = 4; o <= 16; o <<= 1) {
#pragma unroll
        for (int j = 0; j < 8; j++) a[j] += __shfl_xor_sync(0xffffffffu, a[j], o);
    }
    // self loop (after reduction: each lane holds full sums for its fg features)
    {
        int4 v = *(const int4*)(g_tmp + (size_t)n * HID + fg * 8);
        acc8(a, v);
    }
    float di = g_dinv[n];
    if (eidx == 0) {
        float4 bv0 = *(const float4*)(b1 + fg * 8);
        float4 bv1 = *(const float4*)(b1 + fg * 8 + 4);
        float4 y0, y1;
        y0.x = fmaxf(fmaf(di, a[0], bv0.x), 0.0f);
        y0.y = fmaxf(fmaf(di, a[1], bv0.y), 0.0f);
        y0.z = fmaxf(fmaf(di, a[2], bv0.z), 0.0f);
        y0.w = fmaxf(fmaf(di, a[3], bv0.w), 0.0f);
        y1.x = fmaxf(fmaf(di, a[4], bv1.x), 0.0f);
        y1.y = fmaxf(fmaf(di, a[5], bv1.y), 0.0f);
        y1.z = fmaxf(fmaf(di, a[6], bv1.z), 0.0f);
        y1.w = fmaxf(fmaf(di, a[7], bv1.w), 0.0f);
        *(float4*)&sy[w][fg * 8]     = y0;
        *(float4*)&sy[w][fg * 8 + 4] = y1;
    }
    __syncwarp();
    float t = 0.0f;
#pragma unroll
    for (int k = 0; k < HID; k++) t = fmaf(sy[w][k], sW[k * HID + lane], t);
    g_acc[(size_t)n * HID + lane] = __float2half_rn(di * t);
}

// ---------------- fused: agg(L2) + relu + dot W3 + scale -> g_tmp3 ----------------
__global__ void k_agg_xf3(const float* __restrict__ W3, const float* __restrict__ b2) {
    int tid = threadIdx.x;
    int w = tid >> 5, lane = tid & 31;
    int n = blockIdx.x * 8 + w;
    if (n >= N_NODES) return;  // warp-uniform
    int eidx = lane >> 2, fg = lane & 3;
    int e = g_rowptr[n];
    int e1 = g_rowptr[n + 1];
    float a[8] = {0, 0, 0, 0, 0, 0, 0, 0};
    for (; e + 16 <= e1; e += 16) {
        int s0 = g_csr_src[e + eidx];
        int s1 = g_csr_src[e + 8 + eidx];
        int4 v0 = *(const int4*)(g_acc + (size_t)s0 * HID + fg * 8);
        int4 v1 = *(const int4*)(g_acc + (size_t)s1 * HID + fg * 8);
        acc8(a, v0);
        acc8(a, v1);
    }
    if (e + 8 <= e1) {
        int s = g_csr_src[e + eidx];
        int4 v = *(const int4*)(g_acc + (size_t)s * HID + fg * 8);
        acc8(a, v);
        e += 8;
    }
    if (eidx < e1 - e) {
        int s = g_csr_src[e + eidx];
        int4 v = *(const int4*)(g_acc + (size_t)s * HID + fg * 8);
        acc8(a, v);
    }
#pragma unroll
    for (int o = 4; o <= 16; o <<= 1) {
#pragma unroll
        for (int j = 0; j < 8; j++) a[j] += __shfl_xor_sync(0xffffffffu, a[j], o);
    }
    // self loop
    {
        int4 v = *(const int4*)(g_acc + (size_t)n * HID + fg * 8);
        acc8(a, v);
    }
    float di = g_dinv[n];
    float4 bv0 = *(const float4*)(b2 + fg * 8);
    float4 bv1 = *(const float4*)(b2 + fg * 8 + 4);
    float4 wv0 = *(const float4*)(W3 + fg * 8);
    float4 wv1 = *(const float4*)(W3 + fg * 8 + 4);
    float t = fmaxf(fmaf(di, a[0], bv0.x), 0.0f) * wv0.x
            + fmaxf(fmaf(di, a[1], bv0.y), 0.0f) * wv0.y
            + fmaxf(fmaf(di, a[2], bv0.z), 0.0f) * wv0.z
            + fmaxf(fmaf(di, a[3], bv0.w), 0.0f) * wv0.w
            + fmaxf(fmaf(di, a[4], bv1.x), 0.0f) * wv1.x
            + fmaxf(fmaf(di, a[5], bv1.y), 0.0f) * wv1.y
            + fmaxf(fmaf(di, a[6], bv1.z), 0.0f) * wv1.z
            + fmaxf(fmaf(di, a[7], bv1.w), 0.0f) * wv1.w;
    // sum across fg groups (bits 0-1 of lane)
    t += __shfl_xor_sync(0xffffffffu, t, 1);
    t += __shfl_xor_sync(0xffffffffu, t, 2);
    if (lane == 0) g_tmp3[n] = di * t;
}

// ---------------- scalar gather + final sigmoid ----------------
__global__ void k_agg1_final(const float* __restrict__ b3, float* __restrict__ out) {
    int n = blockIdx.x * blockDim.x + threadIdx.x;
    if (n >= N_NODES) return;
    int e = g_rowptr[n];
    int e1 = g_rowptr[n + 1];
    float a = g_tmp3[n];  // self loop
    for (; e + 4 <= e1; e += 4) {
        float v0 = g_tmp3[g_csr_src[e + 0]];
        float v1 = g_tmp3[g_csr_src[e + 1]];
        float v2 = g_tmp3[g_csr_src[e + 2]];
        float v3 = g_tmp3[g_csr_src[e + 3]];
        a += (v0 + v1) + (v2 + v3);
    }
    for (; e < e1; e++) a += g_tmp3[g_csr_src[e]];
    float z = fmaf(g_dinv[n], a, b3[0]);
    out[n] = 1.0f / (1.0f + __expf(-z));
}

extern "C" void kernel_launch(void* const* d_in, const int* in_sizes, int n_in,
                              void* d_out, int out_size) {
    // Resolve inputs by element count — robust to metadata ordering.
    int ix = -1, ie = -1, iw1 = -1, iw2 = -1, ib3 = -1;
    int i32[3], n32 = 0;
    for (int i = 0; i < n_in; i++) {
        switch (in_sizes[i]) {
            case 19200000: ix = i; break;
            case 4800000:  ie = i; break;
            case 4096:     iw1 = i; break;
            case 1024:     iw2 = i; break;
            case 1:        ib3 = i; break;
            case 32:       if (n32 < 3) i32[n32++] = i; break;
            default: break;
        }
    }
    int ib1, ib2, iw3;
    if (ie == 1) {  // dict order: x, edge_index, W1, b1, W2, b2, W3, b3
        ib1 = i32[0]; ib2 = i32[1]; iw3 = i32[2];
    } else {        // alphabetical: W1, W2, W3, b1, b2, b3, edge_index, x
        iw3 = i32[0]; ib1 = i32[1]; ib2 = i32[2];
    }

    const float* x  = (const float*)d_in[ix];
    const int* ei   = (const int*)d_in[ie];   // [2, E] int32
    const float* W1 = (const float*)d_in[iw1];
    const float* b1 = (const float*)d_in[ib1];
    const float* W2 = (const float*)d_in[iw2];
    const float* b2 = (const float*)d_in[ib2];
    const float* W3 = (const float*)d_in[iw3];
    const float* b3 = (const float*)d_in[ib3];
    float* out = (float*)d_out;

    const int* src = ei;
    const int* dst = ei + N_EDGES;

    const int T = 256;
    int nblk_nodes = (N_NODES + T - 1) / T;
    int nblk_rows8 = (N_NODES + 7) / 8;

    // zero counters via memset node (graph-capturable)
    void* cnt_ptr = nullptr;
    cudaGetSymbolAddress(&cnt_ptr, g_cnt);
    cudaMemsetAsync(cnt_ptr, 0, N_NODES * sizeof(int), 0);

    // F1: hist (1/3 of blocks) + wmma xform1 raw (2/3)
    k_F1<<<3 * HIST_BLKS, T>>>(dst, x, W1);
    k_scan_a<<<SCAN_NB, SCAN_BS>>>();
    k_scan_c<<<SCAN_NB, SCAN_BS>>>();   // fused scan_b + scan_c
    // F2: fill (even) + dinv-scale of g_tmp (odd)
    k_F2<<<2 * EDGE_BLKS, T>>>(src, dst);

    k_agg_xf2<<<nblk_rows8, T>>>(W2, b1);    // agg L1 + relu + @W2
    k_agg_xf3<<<nblk_rows8, T>>>(W3, b2);    // agg L2 + relu + dot W3
    k_agg1_final<<<nblk_nodes, T>>>(b3, out);
}